// round 14
// baseline (speedup 1.0000x reference)
#include <cuda_runtime.h>
#include <cuda_bf16.h>
#include <cstdint>

// Conv4D, separable rank-1 kernel k4 = K (x) K, K 3x3.
// Persistent, double-buffered cp.async pipeline: prefetch sample i+2*GRID
// while computing sample i. Pass1 (z,w conv) split across z-halves; pass2
// (x,y conv) split across x-halves. Bank-padded smem, conflict-free.

#define NS 8192
#define GRID 740               // 5 CTAs x 148 SMs
#define THREADS 128
#define IN_STRIDE 68           // floats per (a,b) column, padded 64->68
#define IN_S (64 * IN_STRIDE)  // 4352 floats per buffer
#define TMP_STRIDE 37
#define TMP_SZ (64 * TMP_STRIDE)

__device__ __forceinline__ uint32_t smem_u32(const void* p) {
    uint32_t a;
    asm("{ .reg .u64 t; cvta.to.shared.u64 t, %1; cvt.u32.u64 %0, t; }"
        : "=r"(a) : "l"(p));
    return a;
}
__device__ __forceinline__ void cp16(uint32_t saddr, const void* g) {
    asm volatile("cp.async.cg.shared.global [%0], [%1], 16;" :: "r"(saddr), "l"(g));
}
__device__ __forceinline__ void cp_commit() {
    asm volatile("cp.async.commit_group;");
}
__device__ __forceinline__ void cp_wait1() {
    asm volatile("cp.async.wait_group 1;");
}

__global__ __launch_bounds__(THREADS, 5)
void conv4d_pipe_kernel(const float* __restrict__ in,
                        const float* __restrict__ kern,
                        float* __restrict__ out) {
    __shared__ float s_buf[2 * IN_S + TMP_SZ];   // 44288 B
    float* s_tmp = s_buf + 2 * IN_S;

    const int tid = threadIdx.x;
    const int bid = blockIdx.x;
    const uint32_t sbase = smem_u32(s_buf);

    float k[9];
    #pragma unroll
    for (int i = 0; i < 9; i++) k[i] = __ldg(kern + i);

    // ---- Prefetch helper: stage sample idx into buffer b (coalesced) ----
    auto prefetch = [&](int b, int idx) {
        const float4* __restrict__ g = (const float4*)(in + (size_t)idx * 4096);
        const uint32_t dbase = sbase + (uint32_t)(b * IN_S) * 4u;
        #pragma unroll
        for (int ii = 0; ii < 8; ii++) {
            const int gg = tid + ii * THREADS;   // 0..1023
            const int ab = gg >> 4;
            const int f  = gg & 15;
            cp16(dbase + (uint32_t)(ab * IN_STRIDE + f * 4) * 4u, g + gg);
        }
    };

    // ---- Prolog: fill both buffers ----
    prefetch(0, bid);            cp_commit();
    prefetch(1, bid + GRID);     cp_commit();   // bid+GRID < NS always (740+739)

    for (int it = 0; ; it++) {
        const int i = bid + it * GRID;
        if (i >= NS) break;
        const int cur = it & 1;

        cp_wait1();          // buffer `cur` fully staged
        __syncthreads();     // + prev iteration's pass2 tmp reads are done

        // ---- Pass 1: conv over (z,w). h = z-half, thread owns (h, ab). ----
        {
            const int h  = tid >> 6;          // 0 or 1 (per-warp uniform)
            const int ab = tid & 63;
            const float* base = s_buf + cur * IN_S + ab * IN_STRIDE + h * 24; // h*3 rows
            float* trow = s_tmp + ab * TMP_STRIDE + h * 18;

            float r0[8], r1[8], r2[8];
            #pragma unroll
            for (int b = 0; b < 2; b++) {
                float4 v = ((const float4*)(base + 0))[b];
                r0[4*b+0]=v.x; r0[4*b+1]=v.y; r0[4*b+2]=v.z; r0[4*b+3]=v.w;
                float4 u = ((const float4*)(base + 8))[b];
                r1[4*b+0]=u.x; r1[4*b+1]=u.y; r1[4*b+2]=u.z; r1[4*b+3]=u.w;
            }
            #pragma unroll
            for (int zc = 0; zc < 3; zc++) {
                #pragma unroll
                for (int b = 0; b < 2; b++) {
                    float4 v = ((const float4*)(base + (zc + 2) * 8))[b];
                    r2[4*b+0]=v.x; r2[4*b+1]=v.y; r2[4*b+2]=v.z; r2[4*b+3]=v.w;
                }
                #pragma unroll
                for (int y = 0; y < 6; y++) {
                    trow[zc*6 + y] = k[0]*r0[y] + k[1]*r0[y+1] + k[2]*r0[y+2]
                                   + k[3]*r1[y] + k[4]*r1[y+1] + k[5]*r1[y+2]
                                   + k[6]*r2[y] + k[7]*r2[y+1] + k[8]*r2[y+2];
                }
                #pragma unroll
                for (int b = 0; b < 8; b++) { r0[b] = r1[b]; r1[b] = r2[b]; }
            }
        }
        __syncthreads();     // tmp visible; all reads of buf[cur] complete

        // ---- Prefetch sample i + 2*GRID into the buffer we just freed ----
        {
            const int nxt = i + 2 * GRID;
            if (nxt < NS) prefetch(cur, nxt);
            cp_commit();     // commit even if empty: keeps group accounting exact
        }

        // ---- Pass 2: conv over (x,y). xh = x-half, thread owns (xh, zw). ----
        if (tid < 72) {
            const int xh = tid / 36;
            const int zw = tid - xh * 36;
            const float* tb = s_tmp + zw;
            float* __restrict__ o = out + (size_t)i * 1296;
            const int a0 = xh * 3;

            float r0[8], r1[8], r2[8];
            #pragma unroll
            for (int b = 0; b < 8; b++) {
                r0[b] = tb[((a0 + 0) * 8 + b) * TMP_STRIDE];
                r1[b] = tb[((a0 + 1) * 8 + b) * TMP_STRIDE];
            }
            #pragma unroll
            for (int xc = 0; xc < 3; xc++) {
                #pragma unroll
                for (int b = 0; b < 8; b++)
                    r2[b] = tb[((a0 + xc + 2) * 8 + b) * TMP_STRIDE];
                #pragma unroll
                for (int y = 0; y < 6; y++) {
                    float v = k[0]*r0[y] + k[1]*r0[y+1] + k[2]*r0[y+2]
                            + k[3]*r1[y] + k[4]*r1[y+1] + k[5]*r1[y+2]
                            + k[6]*r2[y] + k[7]*r2[y+1] + k[8]*r2[y+2];
                    o[(a0 + xc) * 216 + y * 36 + zw] = v;
                }
                #pragma unroll
                for (int b = 0; b < 8; b++) { r0[b] = r1[b]; r1[b] = r2[b]; }
            }
        }
    }
}

extern "C" void kernel_launch(void* const* d_in, const int* in_sizes, int n_in,
                              void* d_out, int out_size) {
    const float* input  = (const float*)d_in[0];
    const float* kernel = (const float*)d_in[1];
    float* out = (float*)d_out;
    conv4d_pipe_kernel<<<GRID, THREADS>>>(input, kernel, out);
}